// round 8
// baseline (speedup 1.0000x reference)
#include <cuda_runtime.h>
#include <cstdint>

// Problem constants
#define TT 512
#define BB 128
#define HH 1024
#define SIGMA_REC 0.15811388300841897f   // sqrt(2/0.2)*0.05

// Grid / tiling
#define NCTA 128          // 4 row-blocks x 32 col-blocks
#define NTHREADS 256
#define CK 64             // K chunk
#define NCHUNK (HH / CK)  // 16

// SMEM layout (floats)
#define ASTRIDE 132                 // 64 k-values duplicated (128) + 4 pad -> bank-safe, 16B-aligned rows
#define ABUF (32 * ASTRIDE)         // 4224 floats per A buffer
#define W_FLOATS (HH * 32)          // 32768
#define A_OFF W_FLOATS
#define WIH_OFF (A_OFF + 2 * ABUF)  // 41216
#define BIAS_OFF (WIH_OFF + 64)     // 41280
#define SMEM_FLOATS (BIAS_OFF + 32) // 41312
#define SMEM_BYTES (SMEM_FLOATS * 4) // 165248 B  (< 227 KB limit)

__device__ unsigned g_flags[NCTA];

__global__ void rnn_init_kernel() {
    if (threadIdx.x < NCTA) g_flags[threadIdx.x] = 0u;
}

__device__ __forceinline__ void st_rel(unsigned* p, unsigned v) {
    asm volatile("st.global.release.gpu.u32 [%0], %1;" :: "l"(p), "r"(v) : "memory");
}
__device__ __forceinline__ unsigned ld_acq(const unsigned* p) {
    unsigned v;
    asm volatile("ld.global.acquire.gpu.u32 %0, [%1];" : "=r"(v) : "l"(p) : "memory");
    return v;
}

// All-CTA barrier: per-CTA flag store (release) + every thread polls one flag (acquire).
// 128 CTAs, 1 CTA/SM (forced by 165KB smem), 148 SMs -> co-residency guaranteed.
__device__ __forceinline__ void grid_barrier(unsigned epoch) {
    __syncthreads();
    if (threadIdx.x == 0) st_rel(&g_flags[blockIdx.x], epoch);
    const unsigned idx = threadIdx.x & (NCTA - 1);
    while (ld_acq(&g_flags[idx]) < epoch) { }
    __syncthreads();
}

__global__ void __launch_bounds__(NTHREADS, 1)
rnn_persistent_kernel(const float* __restrict__ inp,
                      const float* __restrict__ init_state,
                      const float* __restrict__ noise,
                      const float* __restrict__ wih,
                      const float* __restrict__ whh,
                      const float* __restrict__ bias,
                      float* __restrict__ out)
{
    extern __shared__ float sm[];
    float* sW    = sm;              // [1024][32]  W_hh strip for this CTA's 32 cols
    float* sA    = sm + A_OFF;      // [2][32][132] relu(state) rows, duplicated pairs {a,a}
    float* sWih  = sm + WIH_OFF;    // [2][32]
    float* sBias = sm + BIAS_OFF;   // [32]

    const int tid  = threadIdx.x;
    const int cta  = blockIdx.x;
    const int row0 = (cta >> 5) * 32;   // batch-row block (4 blocks of 32)
    const int col0 = (cta & 31) * 32;   // hidden-col block (32 blocks of 32)

    // One-time: stage W strip into SMEM
    for (int idx = tid; idx < W_FLOATS; idx += NTHREADS) {
        const int k = idx >> 5, c = idx & 31;
        sW[idx] = whh[k * HH + col0 + c];
    }
    if (tid < 32) {
        sWih[tid]      = wih[col0 + tid];
        sWih[32 + tid] = wih[HH + col0 + tid];
        sBias[tid]     = bias[col0 + tid];
    }

    // Output mapping: warp footprint = 8 rows x 16 cols (minimizes unique SMEM bytes/warp).
    const int wid    = tid >> 5;
    const int lane   = tid & 31;
    const int rowblk = wid & 3;     // 0..3  (8 rows each)
    const int colblk = wid >> 2;    // 0..1  (16 cols each)
    const int rl     = lane >> 2;   // 0..7
    const int cgl    = lane & 3;    // 0..3
    const int r      = rowblk * 8 + rl;       // local row 0..31
    const int cl     = colblk * 16 + cgl * 4; // local col, step 4
    const int grow   = row0 + r;
    const int gcol   = col0 + cl;

    // A-loader mapping: 512 float4 per chunk (32 rows x 16 quads)
    const int l_r0  = tid >> 4;          // rows 0..15
    const int l_kq  = tid & 15;
    const int l_r1  = l_r0 + 16;         // rows 16..31

    // Write out[0] = initial_state (tile-wise; union over CTAs covers all of it)
    {
        const float4 v = *(const float4*)&init_state[grow * HH + gcol];
        *(float4*)&out[grow * HH + gcol] = v;
    }
    grid_barrier(1u);

    #pragma unroll 1
    for (int t = 0; t < TT; ++t) {
        const float* Ot = out + (size_t)t * (BB * HH);
        float*       On = out + (size_t)(t + 1) * (BB * HH);

        // Prefetch epilogue operands early (hide HBM/L2 latency under GEMM)
        const float4 nz   = *(const float4*)&noise[((size_t)t * BB + grow) * HH + gcol];
        const float2 iv   = *(const float2*)&inp[((size_t)t * BB + grow) * 2];
        const float4 old4 = *(const float4*)&Ot[grow * HH + gcol];

        // Load K-chunk 0: relu + duplicate into pairs {a,a}
        {
            float4 v0 = *(const float4*)&Ot[(row0 + l_r0) * HH + l_kq * 4];
            float4 v1 = *(const float4*)&Ot[(row0 + l_r1) * HH + l_kq * 4];
            v0.x = fmaxf(v0.x, 0.f); v0.y = fmaxf(v0.y, 0.f); v0.z = fmaxf(v0.z, 0.f); v0.w = fmaxf(v0.w, 0.f);
            v1.x = fmaxf(v1.x, 0.f); v1.y = fmaxf(v1.y, 0.f); v1.z = fmaxf(v1.z, 0.f); v1.w = fmaxf(v1.w, 0.f);
            float* d0 = &sA[l_r0 * ASTRIDE + l_kq * 8];
            ((float4*)d0)[0] = make_float4(v0.x, v0.x, v0.y, v0.y);
            ((float4*)d0)[1] = make_float4(v0.z, v0.z, v0.w, v0.w);
            float* d1 = &sA[l_r1 * ASTRIDE + l_kq * 8];
            ((float4*)d1)[0] = make_float4(v1.x, v1.x, v1.y, v1.y);
            ((float4*)d1)[1] = make_float4(v1.z, v1.z, v1.w, v1.w);
        }
        __syncthreads();

        unsigned long long acc01 = 0ull, acc23 = 0ull;

        #pragma unroll 1
        for (int ck = 0; ck < NCHUNK; ++ck) {
            // Prefetch next chunk into registers (overlaps with compute below)
            float4 v0, v1;
            const int nb = (ck + 1) & 1;
            if (ck < NCHUNK - 1) {
                const int kb = (ck + 1) * CK;
                v0 = *(const float4*)&Ot[(row0 + l_r0) * HH + kb + l_kq * 4];
                v1 = *(const float4*)&Ot[(row0 + l_r1) * HH + kb + l_kq * 4];
            }

            // Inner product over this chunk: LDS.64 (dup a) + LDS.128 (4 W cols) + 2x fma.f32x2
            const float* aRow = &sA[(ck & 1) * ABUF + r * ASTRIDE];
            const float* wPtr = &sW[ck * CK * 32 + cl];
            #pragma unroll
            for (int kk = 0; kk < CK; ++kk) {
                const unsigned long long a2 = *(const unsigned long long*)(aRow + 2 * kk);
                const ulonglong2 w = *(const ulonglong2*)(wPtr + kk * 32);
                asm("fma.rn.f32x2 %0, %1, %2, %0;" : "+l"(acc01) : "l"(a2), "l"(w.x));
                asm("fma.rn.f32x2 %0, %1, %2, %0;" : "+l"(acc23) : "l"(a2), "l"(w.y));
            }

            if (ck < NCHUNK - 1) {
                v0.x = fmaxf(v0.x, 0.f); v0.y = fmaxf(v0.y, 0.f); v0.z = fmaxf(v0.z, 0.f); v0.w = fmaxf(v0.w, 0.f);
                v1.x = fmaxf(v1.x, 0.f); v1.y = fmaxf(v1.y, 0.f); v1.z = fmaxf(v1.z, 0.f); v1.w = fmaxf(v1.w, 0.f);
                float* d0 = &sA[nb * ABUF + l_r0 * ASTRIDE + l_kq * 8];
                ((float4*)d0)[0] = make_float4(v0.x, v0.x, v0.y, v0.y);
                ((float4*)d0)[1] = make_float4(v0.z, v0.z, v0.w, v0.w);
                float* d1 = &sA[nb * ABUF + l_r1 * ASTRIDE + l_kq * 8];
                ((float4*)d1)[0] = make_float4(v1.x, v1.x, v1.y, v1.y);
                ((float4*)d1)[1] = make_float4(v1.z, v1.z, v1.w, v1.w);
                __syncthreads();
            }
        }

        // Unpack accumulators
        float c0, c1, c2, c3;
        {
            unsigned u0, u1, u2, u3;
            asm("mov.b64 {%0, %1}, %2;" : "=r"(u0), "=r"(u1) : "l"(acc01));
            asm("mov.b64 {%0, %1}, %2;" : "=r"(u2), "=r"(u3) : "l"(acc23));
            c0 = __uint_as_float(u0); c1 = __uint_as_float(u1);
            c2 = __uint_as_float(u2); c3 = __uint_as_float(u3);
        }

        // Epilogue: drive = inp@Wih + bias + noise*SIGMA; state = 0.8*old + 0.2*(mat + drive)
        const float wa0 = sWih[cl],      wa1 = sWih[cl + 1],      wa2 = sWih[cl + 2],      wa3 = sWih[cl + 3];
        const float wb0 = sWih[32 + cl], wb1 = sWih[32 + cl + 1], wb2 = sWih[32 + cl + 2], wb3 = sWih[32 + cl + 3];
        const float b0  = sBias[cl],     b1  = sBias[cl + 1],     b2  = sBias[cl + 2],     b3  = sBias[cl + 3];

        float4 res;
        res.x = 0.8f * old4.x + 0.2f * (c0 + iv.x * wa0 + iv.y * wb0 + b0 + SIGMA_REC * nz.x);
        res.y = 0.8f * old4.y + 0.2f * (c1 + iv.x * wa1 + iv.y * wb1 + b1 + SIGMA_REC * nz.y);
        res.z = 0.8f * old4.z + 0.2f * (c2 + iv.x * wa2 + iv.y * wb2 + b2 + SIGMA_REC * nz.z);
        res.w = 0.8f * old4.w + 0.2f * (c3 + iv.x * wa3 + iv.y * wb3 + b3 + SIGMA_REC * nz.w);
        *(float4*)&On[grow * HH + gcol] = res;

        grid_barrier((unsigned)(t + 2));
    }
}

extern "C" void kernel_launch(void* const* d_in, const int* in_sizes, int n_in,
                              void* d_out, int out_size) {
    const float* inp   = (const float*)d_in[0];  // [512,128,2]
    const float* inis  = (const float*)d_in[1];  // [128,1024]
    const float* noise = (const float*)d_in[2];  // [512,128,1024]
    const float* wih   = (const float*)d_in[3];  // [2,1024]
    const float* whh   = (const float*)d_in[4];  // [1024,1024]
    const float* bias  = (const float*)d_in[5];  // [1,1024]
    float* out = (float*)d_out;                  // [513,128,1024]

    cudaFuncSetAttribute(rnn_persistent_kernel,
                         cudaFuncAttributeMaxDynamicSharedMemorySize, SMEM_BYTES);

    rnn_init_kernel<<<1, 128>>>();
    rnn_persistent_kernel<<<NCTA, NTHREADS, SMEM_BYTES>>>(inp, inis, noise, wih, whh, bias, out);
}